// round 3
// baseline (speedup 1.0000x reference)
#include <cuda_runtime.h>
#include <math.h>

// Problem constants
#define T_  4
#define B_  4
#define C_  256
#define H_  32
#define W_  32
#define TB_ 16          // T_*B_
#define HH_ 16
#define WH_ 16
#define RS2 0.70710678f // 1/sqrt(2) (float32)

// ---- scratch (device globals; no allocation allowed) ----
__device__ float g_s  [T_*B_*C_*H_*W_];      // spikes (0/1)
__device__ float g_l1 [TB_*2*C_*H_*WH_];     // pre-BN level-1 coeffs
__device__ float g_l2 [TB_*4*C_*HH_*WH_];    // pre-BN level-2 coeffs
__device__ float g_mix[TB_*4*C_*HH_*WH_];    // post channel-mix
__device__ float g_rec[TB_*C_*H_*W_];        // pre-BN reconstruction
__device__ float g_c1 [TB_*C_*H_*W_];        // pre-BN conv1 out
__device__ float g_c2 [TB_*C_*H_*W_];        // pre-BN conv2 out
__device__ float2 g_stat_fwd[512];           // (mean, rstd)
__device__ float2 g_stat_mul[1024];
__device__ float2 g_stat_inv[256];
__device__ float2 g_stat_c1 [256];
__device__ float2 g_stat_c2 [256];

// ============================================================
// K1: LIF over T (sequential, in-thread) + Haar along W + L1 gate
// thread <-> (b, c, h, wpair); 524288 threads
// ============================================================
__global__ void k_lif_haarw(const float* __restrict__ x) {
    int idx = blockIdx.x * 256 + threadIdx.x;
    int wp = idx & 15;
    int h  = (idx >> 4) & 31;
    int c  = (idx >> 9) & 255;
    int b  = idx >> 17;

    float v0 = 0.f, v1 = 0.f;
    #pragma unroll
    for (int t = 0; t < T_; t++) {
        size_t base = ((((size_t)t*B_ + b)*C_ + c)*H_ + h)*W_ + 2*wp;
        float x0 = x[base], x1 = x[base + 1];
        v0 += (x0 - v0) * 0.5f;
        float s0 = (v0 >= 1.0f) ? 1.0f : 0.0f;
        v0 *= (1.0f - s0);
        v1 += (x1 - v1) * 0.5f;
        float s1 = (v1 >= 1.0f) ? 1.0f : 0.0f;
        v1 *= (1.0f - s1);
        g_s[base] = s0;
        g_s[base + 1] = s1;

        float low  = RS2 * (s0 + s1);
        float high = RS2 * (s0 - s1);
        if (fabsf(low)  < 0.5f) low  = 0.f;   // c * spike(|c|-0.5)
        if (fabsf(high) < 0.5f) high = 0.f;
        int tb = t*B_ + b;
        size_t l1b = (((size_t)tb*512 + c)*H_ + h)*WH_ + wp;
        g_l1[l1b]          = low;                // channel c
        g_l1[l1b + 131072] = high;               // channel C_+c (256*512)
    }
}

// ============================================================
// generic per-channel stats (deterministic single-block tree)
// layout: (TB_, nch, spatial). out = (mean, rsqrt(var+eps))
// which: 0=l1, 1=l2, 2=rec, 3=c1, 4=c2
// ============================================================
__global__ void k_stats(int which, int nch, int spatial) {
    const float* src =
        which == 0 ? g_l1 : which == 1 ? g_l2 :
        which == 2 ? g_rec : which == 3 ? g_c1 : g_c2;
    float2* out =
        which == 0 ? g_stat_fwd : which == 1 ? g_stat_mul :
        which == 2 ? g_stat_inv : which == 3 ? g_stat_c1 : g_stat_c2;

    int ch = blockIdx.x;
    float s = 0.f, q = 0.f;
    for (int tb = 0; tb < TB_; tb++) {
        const float* p = src + ((size_t)tb * nch + ch) * spatial;
        for (int j = threadIdx.x; j < spatial; j += 256) {
            float v = p[j];
            s += v; q += v * v;
        }
    }
    __shared__ float ss[256], sq[256];
    ss[threadIdx.x] = s; sq[threadIdx.x] = q;
    __syncthreads();
    for (int off = 128; off > 0; off >>= 1) {
        if (threadIdx.x < off) {
            ss[threadIdx.x] += ss[threadIdx.x + off];
            sq[threadIdx.x] += sq[threadIdx.x + off];
        }
        __syncthreads();
    }
    if (threadIdx.x == 0) {
        float n = 16.0f * (float)spatial;
        float mean = ss[0] / n;
        float var  = sq[0] / n - mean * mean;
        out[ch] = make_float2(mean, rsqrtf(var + 1e-5f));
    }
}

// ============================================================
// K3: apply bn_fwd, Haar along H, threshold + band energy gate
// block <-> (tb, c); thread <-> (v, w) quarter-res position
// ============================================================
__global__ void k_haarh_gate(const float* __restrict__ gf,
                             const float* __restrict__ bf) {
    int tb = blockIdx.x >> 8;
    int c  = blockIdx.x & 255;
    int t  = threadIdx.x;
    int v  = t >> 4, w = t & 15;

    float2 stl = g_stat_fwd[c];
    float2 sth = g_stat_fwd[256 + c];
    float alo = gf[c] * stl.y,       clo = bf[c]       - stl.x * alo;
    float ahi = gf[256 + c] * sth.y, chi = bf[256 + c] - sth.x * ahi;

    size_t lo_base = ((size_t)tb*512 + c) * 512;   // *H_*WH_
    size_t hi_base = lo_base + 131072;
    float a0 = g_l1[lo_base + (2*v  )*16 + w] * alo + clo;
    float a1 = g_l1[lo_base + (2*v+1)*16 + w] * alo + clo;
    float b0 = g_l1[hi_base + (2*v  )*16 + w] * ahi + chi;
    float b1 = g_l1[hi_base + (2*v+1)*16 + w] * ahi + chi;

    float LL = RS2 * (a0 + a1);
    float HL = RS2 * (a0 - a1);
    float LH = RS2 * (b0 + b1);
    float HH = RS2 * (b0 - b1);
    if (fabsf(LL) < 0.5f) LL = 0.f;
    if (fabsf(HL) < 0.5f) HL = 0.f;
    if (fabsf(LH) < 0.5f) LH = 0.f;
    if (fabsf(HH) < 0.5f) HH = 0.f;

    __shared__ float4 red[256];
    __shared__ float4 flags;
    red[t] = make_float4(LL*LL, HL*HL, LH*LH, HH*HH);
    __syncthreads();
    for (int off = 128; off > 0; off >>= 1) {
        if (t < off) {
            float4 a = red[t], b4 = red[t + off];
            red[t] = make_float4(a.x + b4.x, a.y + b4.y, a.z + b4.z, a.w + b4.w);
        }
        __syncthreads();
    }
    if (t == 0) {
        float4 e = red[0];
        const float inv = 1.0f / 256.0f;
        flags = make_float4(e.x * inv > 0.01f ? 1.f : 0.f,
                            e.y * inv > 0.02f ? 1.f : 0.f,
                            e.z * inv > 0.02f ? 1.f : 0.f,
                            e.w * inv > 0.05f ? 1.f : 0.f);
    }
    __syncthreads();

    size_t ob = (((size_t)tb*1024 + c)*16 + v)*16 + w;
    g_l2[ob]           = LL * flags.x;
    g_l2[ob + 65536]   = HL * flags.y;   // +256 channels
    g_l2[ob + 131072]  = LH * flags.z;
    g_l2[ob + 196608]  = HH * flags.w;
}

// ============================================================
// K5: apply bn_mul + 16x16 channel mix per group g (g = ch/16, nb = g/4)
// block <-> (tb, g); thread <-> spatial position p (256)
// ============================================================
__global__ void k_mix(const float* __restrict__ hw,
                      const float* __restrict__ gm,
                      const float* __restrict__ bm) {
    int tb = blockIdx.x >> 6;
    int g  = blockIdx.x & 63;
    int nb = g >> 2;
    __shared__ float Wsm[256];
    __shared__ float sc[16], of[16];
    int t = threadIdx.x;
    Wsm[t] = hw[nb * 256 + t];   // W[d][k] = hw[nb,d,k]
    if (t < 16) {
        int ch = g * 16 + t;
        float2 st = g_stat_mul[ch];
        float a = gm[ch] * st.y;
        sc[t] = a;
        of[t] = bm[ch] - st.x * a;
    }
    __syncthreads();

    float acc[16];
    #pragma unroll
    for (int k = 0; k < 16; k++) acc[k] = 0.f;
    size_t base = ((size_t)tb*1024 + g*16) * 256 + t;
    #pragma unroll
    for (int d = 0; d < 16; d++) {
        float in = g_l2[base + (size_t)d*256] * sc[d] + of[d];
        #pragma unroll
        for (int k = 0; k < 16; k++) acc[k] += in * Wsm[d*16 + k];
    }
    #pragma unroll
    for (int k = 0; k < 16; k++) g_mix[base + (size_t)k*256] = acc[k];
}

// ============================================================
// K6: inverse Haar H then W — pure per-thread 4->4 butterfly (2x2 patch)
// block <-> (tb, c); thread <-> (i, j)
// ============================================================
__global__ void k_invhaar() {
    int tb = blockIdx.x >> 8;
    int c  = blockIdx.x & 255;
    int t  = threadIdx.x;
    int i  = t >> 4, j = t & 15;

    size_t b0 = (((size_t)tb*1024 + c)*16 + i)*16 + j;
    float LL = g_mix[b0];
    float HL = g_mix[b0 + 65536];
    float LH = g_mix[b0 + 131072];
    float HH = g_mix[b0 + 196608];

    float lo0 = RS2 * (LL + HL), lo1 = RS2 * (LL - HL);
    float hi0 = RS2 * (LH + HH), hi1 = RS2 * (LH - HH);

    size_t rb = (((size_t)tb*256 + c)*32 + 2*i)*32 + 2*j;
    *reinterpret_cast<float2*>(&g_rec[rb])      = make_float2(RS2*(lo0+hi0), RS2*(lo0-hi0));
    *reinterpret_cast<float2*>(&g_rec[rb + 32]) = make_float2(RS2*(lo1+hi1), RS2*(lo1-hi1));
}

// ============================================================
// K8: grouped 1x1 conv (16-ch groups). BN cancels the bias -> dropped.
// block <-> image (tb*16+nb); 256 threads x 4 pixels
// ============================================================
__global__ void k_conv1(const float* __restrict__ w1) {
    int im = blockIdx.x;
    int tb = im >> 4, nb = im & 15;
    __shared__ float Wsm[256];
    Wsm[threadIdx.x] = w1[threadIdx.x];   // w1[o*16+i]
    __syncthreads();
    size_t sbase = ((size_t)tb*256 + nb*16) * 1024;
    for (int p = threadIdx.x; p < 1024; p += 256) {
        float sin[16];
        #pragma unroll
        for (int i = 0; i < 16; i++) sin[i] = g_s[sbase + (size_t)i*1024 + p];
        #pragma unroll
        for (int o = 0; o < 16; o++) {
            float a = 0.f;
            #pragma unroll
            for (int i = 0; i < 16; i++) a += Wsm[o*16 + i] * sin[i];
            g_c1[sbase + (size_t)o*1024 + p] = a;
        }
    }
}

// ============================================================
// K9: grouped 3x3 SAME conv. smem tile stride 35 (conflict-free for
// row-indexed lanes), two 8-channel phases to stay < 48KB static smem.
// block <-> image; thread <-> (o, h); 32-wide register row accumulator.
// ============================================================
#define TROW 35
#define TCH  (34 * TROW)   // 1190 floats per channel slab

__global__ __launch_bounds__(512) void k_conv2(const float* __restrict__ w2) {
    int im = blockIdx.x;
    int tb = im >> 4, nb = im & 15;
    __shared__ float tile[8 * TCH];   // 38080 B
    __shared__ float Wsm[2304];       //  9216 B
    int tid = threadIdx.x;

    for (int idx = tid; idx < 2304; idx += 512) Wsm[idx] = w2[idx];
    for (int idx = tid; idx < 8 * TCH; idx += 512) tile[idx] = 0.f;

    size_t sbase = ((size_t)tb*256 + nb*16) * 1024;
    int o = tid >> 5, h = tid & 31;

    float acc[32];
    #pragma unroll
    for (int w = 0; w < 32; w++) acc[w] = 0.f;

    for (int ph = 0; ph < 2; ph++) {
        __syncthreads();  // also covers zero-init / previous-phase reads
        for (int idx = tid; idx < 8192; idx += 512) {
            int ii = idx >> 10;
            int hh = (idx >> 5) & 31;
            int ww = idx & 31;
            tile[ii*TCH + (hh+1)*TROW + (ww+1)] =
                g_s[sbase + (size_t)(ph*8 + ii)*1024 + hh*32 + ww];
        }
        __syncthreads();

        for (int ii = 0; ii < 8; ii++) {
            int ic = ph*8 + ii;
            float wk[9];
            #pragma unroll
            for (int k = 0; k < 9; k++) wk[k] = Wsm[o*144 + ic*9 + k];
            #pragma unroll
            for (int ky = 0; ky < 3; ky++) {
                const float* row = &tile[ii*TCH + (h + ky)*TROW];
                float t0 = row[0], t1 = row[1];
                #pragma unroll
                for (int w = 0; w < 32; w++) {
                    float t2 = row[w + 2];
                    acc[w] += wk[ky*3] * t0 + wk[ky*3+1] * t1 + wk[ky*3+2] * t2;
                    t0 = t1; t1 = t2;
                }
            }
        }
    }

    size_t ob = sbase + (size_t)o*1024 + h*32;
    #pragma unroll
    for (int w = 0; w < 32; w++) g_c2[ob + w] = acc[w];
}

// ============================================================
// K12: out = BN_inv(rec) + BN_c1(c1) + BN_c2(c2)
// ============================================================
__global__ void k_final(float* __restrict__ out,
                        const float* __restrict__ gi, const float* __restrict__ bi,
                        const float* __restrict__ g1, const float* __restrict__ b1,
                        const float* __restrict__ g2, const float* __restrict__ b2) {
    size_t idx = (size_t)blockIdx.x * 256 + threadIdx.x;
    int ch = (int)((idx >> 10) & 255);
    float2 si = g_stat_inv[ch], s1 = g_stat_c1[ch], s2 = g_stat_c2[ch];
    float ai = gi[ch] * si.y, ci  = bi[ch] - si.x * ai;
    float a1 = g1[ch] * s1.y, c1o = b1[ch] - s1.x * a1;
    float a2 = g2[ch] * s2.y, c2o = b2[ch] - s2.x * a2;
    out[idx] = (g_rec[idx] * ai + ci)
             + (g_c1[idx]  * a1 + c1o)
             + (g_c2[idx]  * a2 + c2o);
}

// ============================================================
extern "C" void kernel_launch(void* const* d_in, const int* in_sizes, int n_in,
                              void* d_out, int out_size) {
    const float* x        = (const float*)d_in[0];
    const float* haar_w   = (const float*)d_in[1];
    const float* conv1_w  = (const float*)d_in[2];
    // d_in[3] conv1_b, d_in[5] conv2_b: cancelled by BN, unused
    const float* conv2_w  = (const float*)d_in[4];
    const float* bn_fwd_g = (const float*)d_in[6];
    const float* bn_fwd_b = (const float*)d_in[7];
    const float* bn_mul_g = (const float*)d_in[8];
    const float* bn_mul_b = (const float*)d_in[9];
    const float* bn_inv_g = (const float*)d_in[10];
    const float* bn_inv_b = (const float*)d_in[11];
    const float* bn_c1_g  = (const float*)d_in[12];
    const float* bn_c1_b  = (const float*)d_in[13];
    const float* bn_c2_g  = (const float*)d_in[14];
    const float* bn_c2_b  = (const float*)d_in[15];
    float* out = (float*)d_out;

    k_lif_haarw<<<2048, 256>>>(x);
    k_stats<<<512, 256>>>(0, 512, 512);                 // bn_fwd stats
    k_haarh_gate<<<4096, 256>>>(bn_fwd_g, bn_fwd_b);
    k_stats<<<1024, 256>>>(1, 1024, 256);               // bn_mul stats
    k_mix<<<1024, 256>>>(haar_w, bn_mul_g, bn_mul_b);
    k_invhaar<<<4096, 256>>>();
    k_stats<<<256, 256>>>(2, 256, 1024);                // bn_inv stats
    k_conv1<<<256, 256>>>(conv1_w);
    k_conv2<<<256, 512>>>(conv2_w);
    k_stats<<<256, 256>>>(3, 256, 1024);                // bn_c1 stats
    k_stats<<<256, 256>>>(4, 256, 1024);                // bn_c2 stats
    k_final<<<16384, 256>>>(out, bn_inv_g, bn_inv_b,
                            bn_c1_g, bn_c1_b, bn_c2_g, bn_c2_b);
}

// round 5
// speedup vs baseline: 1.3438x; 1.3438x over previous
#include <cuda_runtime.h>
#include <math.h>

#define RS2 0.70710678f // 1/sqrt(2)

// ---- scratch (device globals; no allocation allowed) ----
__device__ float g_s  [4*4*256*32*32];      // spikes (0/1)
__device__ float g_l1 [16*512*32*16];       // pre-BN level-1 coeffs
__device__ float g_l2 [16*1024*16*16];      // pre-BN level-2 coeffs
__device__ float g_mix[16*1024*16*16];      // post channel-mix
__device__ float g_rec[16*256*32*32];       // pre-BN reconstruction
__device__ float g_c1 [16*256*32*32];       // pre-BN conv1 out
__device__ float g_c2 [16*256*32*32];       // pre-BN conv2 out
// per-(channel, slot) partial (sum, sumsq) — fixed slots => deterministic
__device__ float2 g_part_fwd[512*8];
__device__ float2 g_part_mul[1024*16];
__device__ float2 g_part_inv[256*16];
__device__ float2 g_part_c1 [256*16];
__device__ float2 g_part_c2 [256*16];

// ============================================================
// K1: LIF over T + Haar along W + L1 gate + bn_fwd partials
// block: fixed (b, c, h-half); threads (h_lo, wpair)
// ============================================================
__global__ void k_lif_haarw(const float* __restrict__ x) {
    int blk = blockIdx.x, t = threadIdx.x;
    int idx = blk * 256 + t;
    int wp = idx & 15;
    int h  = (idx >> 4) & 31;
    int c  = (idx >> 9) & 255;
    int b  = idx >> 17;

    float v0 = 0.f, v1 = 0.f;
    float4 ps = make_float4(0.f, 0.f, 0.f, 0.f); // sum_lo, sq_lo, sum_hi, sq_hi
    #pragma unroll
    for (int tt = 0; tt < 4; tt++) {
        size_t base = ((((size_t)tt*4 + b)*256 + c)*32 + h)*32 + 2*wp;
        float2 xx = *reinterpret_cast<const float2*>(&x[base]);
        v0 += (xx.x - v0) * 0.5f;
        float s0 = (v0 >= 1.0f) ? 1.0f : 0.0f;
        v0 *= (1.0f - s0);
        v1 += (xx.y - v1) * 0.5f;
        float s1 = (v1 >= 1.0f) ? 1.0f : 0.0f;
        v1 *= (1.0f - s1);
        *reinterpret_cast<float2*>(&g_s[base]) = make_float2(s0, s1);

        float low  = RS2 * (s0 + s1);
        float high = RS2 * (s0 - s1);
        if (fabsf(low)  < 0.5f) low  = 0.f;
        if (fabsf(high) < 0.5f) high = 0.f;
        int tb = tt*4 + b;
        size_t l1b = (((size_t)tb*512 + c)*32 + h)*16 + wp;
        g_l1[l1b]          = low;
        g_l1[l1b + 131072] = high;
        ps.x += low;  ps.y += low*low;
        ps.z += high; ps.w += high*high;
    }
    #pragma unroll
    for (int off = 16; off; off >>= 1) {
        ps.x += __shfl_down_sync(0xffffffffu, ps.x, off);
        ps.y += __shfl_down_sync(0xffffffffu, ps.y, off);
        ps.z += __shfl_down_sync(0xffffffffu, ps.z, off);
        ps.w += __shfl_down_sync(0xffffffffu, ps.w, off);
    }
    __shared__ float4 wsum[8];
    if ((t & 31) == 0) wsum[t >> 5] = ps;
    __syncthreads();
    if (t == 0) {
        float4 a = wsum[0];
        #pragma unroll
        for (int i = 1; i < 8; i++) {
            float4 w4 = wsum[i];
            a.x += w4.x; a.y += w4.y; a.z += w4.z; a.w += w4.w;
        }
        int slot = ((blk >> 9) << 1) | (blk & 1);   // b*2 + hhalf
        int cc   = (blk >> 1) & 255;
        g_part_fwd[cc*8 + slot]        = make_float2(a.x, a.y);
        g_part_fwd[(256 + cc)*8 + slot] = make_float2(a.z, a.w);
    }
}

// ============================================================
// K2: inline bn_fwd stats + Haar along H + threshold + band gate
//     + bn_mul partials. block <-> (tb, c)
// ============================================================
__global__ void k_haarh_gate(const float* __restrict__ gf,
                             const float* __restrict__ bf) {
    int tb = blockIdx.x >> 8;
    int c  = blockIdx.x & 255;
    int t  = threadIdx.x;

    __shared__ float2 coef[2];   // (scale, offset) for low / high channel
    if (t < 16) {
        int chn = (t < 8) ? c : 256 + c;
        float2 p = g_part_fwd[chn*8 + (t & 7)];
        float s = p.x, q = p.y;
        #pragma unroll
        for (int off = 4; off; off >>= 1) {
            s += __shfl_down_sync(0xffffu, s, off, 8);
            q += __shfl_down_sync(0xffffu, q, off, 8);
        }
        if ((t & 7) == 0) {
            float mean = s * (1.0f/8192.0f);
            float var  = q * (1.0f/8192.0f) - mean*mean;
            float a = gf[chn] * rsqrtf(var + 1e-5f);
            coef[t >> 3] = make_float2(a, bf[chn] - mean*a);
        }
    }
    __syncthreads();

    int v = t >> 4, w = t & 15;
    float alo = coef[0].x, clo = coef[0].y;
    float ahi = coef[1].x, chi = coef[1].y;

    size_t lo_base = ((size_t)tb*512 + c) * 512;
    size_t hi_base = lo_base + 131072;
    float a0 = g_l1[lo_base + (2*v  )*16 + w] * alo + clo;
    float a1 = g_l1[lo_base + (2*v+1)*16 + w] * alo + clo;
    float b0 = g_l1[hi_base + (2*v  )*16 + w] * ahi + chi;
    float b1 = g_l1[hi_base + (2*v+1)*16 + w] * ahi + chi;

    float LL = RS2 * (a0 + a1);
    float HL = RS2 * (a0 - a1);
    float LH = RS2 * (b0 + b1);
    float HH = RS2 * (b0 - b1);
    if (fabsf(LL) < 0.5f) LL = 0.f;
    if (fabsf(HL) < 0.5f) HL = 0.f;
    if (fabsf(LH) < 0.5f) LH = 0.f;
    if (fabsf(HH) < 0.5f) HH = 0.f;

    float4 vs = make_float4(LL, HL, LH, HH);
    float4 vq = make_float4(LL*LL, HL*HL, LH*LH, HH*HH);
    #pragma unroll
    for (int off = 16; off; off >>= 1) {
        vs.x += __shfl_down_sync(0xffffffffu, vs.x, off);
        vs.y += __shfl_down_sync(0xffffffffu, vs.y, off);
        vs.z += __shfl_down_sync(0xffffffffu, vs.z, off);
        vs.w += __shfl_down_sync(0xffffffffu, vs.w, off);
        vq.x += __shfl_down_sync(0xffffffffu, vq.x, off);
        vq.y += __shfl_down_sync(0xffffffffu, vq.y, off);
        vq.z += __shfl_down_sync(0xffffffffu, vq.z, off);
        vq.w += __shfl_down_sync(0xffffffffu, vq.w, off);
    }
    __shared__ float4 wS[8], wQ[8];
    __shared__ float4 flags;
    if ((t & 31) == 0) { wS[t >> 5] = vs; wQ[t >> 5] = vq; }
    __syncthreads();
    if (t == 0) {
        float4 S = wS[0], Q = wQ[0];
        #pragma unroll
        for (int i = 1; i < 8; i++) {
            float4 a = wS[i], b4 = wQ[i];
            S.x += a.x;  S.y += a.y;  S.z += a.z;  S.w += a.w;
            Q.x += b4.x; Q.y += b4.y; Q.z += b4.z; Q.w += b4.w;
        }
        const float inv = 1.0f / 256.0f;
        float4 f = make_float4(Q.x*inv > 0.01f ? 1.f : 0.f,
                               Q.y*inv > 0.02f ? 1.f : 0.f,
                               Q.z*inv > 0.02f ? 1.f : 0.f,
                               Q.w*inv > 0.05f ? 1.f : 0.f);
        flags = f;
        // bn_mul partials (gated values => multiply by flag)
        g_part_mul[(c        )*16 + tb] = make_float2(f.x*S.x, f.x*Q.x);
        g_part_mul[(c + 256  )*16 + tb] = make_float2(f.y*S.y, f.y*Q.y);
        g_part_mul[(c + 512  )*16 + tb] = make_float2(f.z*S.z, f.z*Q.z);
        g_part_mul[(c + 768  )*16 + tb] = make_float2(f.w*S.w, f.w*Q.w);
    }
    __syncthreads();

    size_t ob = (((size_t)tb*1024 + c)*16 + v)*16 + w;
    g_l2[ob]          = LL * flags.x;
    g_l2[ob + 65536]  = HL * flags.y;
    g_l2[ob + 131072] = LH * flags.z;
    g_l2[ob + 196608] = HH * flags.w;
}

// ============================================================
// K3: inline bn_mul stats + 16x16 channel mix. block <-> (tb, g)
// ============================================================
__global__ void k_mix(const float* __restrict__ hw,
                      const float* __restrict__ gm,
                      const float* __restrict__ bm) {
    int tb = blockIdx.x >> 6;
    int g  = blockIdx.x & 63;
    int nb = g >> 2;
    __shared__ float Wsm[256];
    __shared__ float sc[16], of[16];
    int t = threadIdx.x;
    Wsm[t] = hw[nb * 256 + t];
    {
        int chl = t >> 4, slot = t & 15;
        int ch = g*16 + chl;
        float2 p = g_part_mul[ch*16 + slot];
        float s = p.x, q = p.y;
        #pragma unroll
        for (int off = 8; off; off >>= 1) {
            s += __shfl_down_sync(0xffffffffu, s, off, 16);
            q += __shfl_down_sync(0xffffffffu, q, off, 16);
        }
        if (slot == 0) {
            float mean = s * (1.0f/4096.0f);
            float var  = q * (1.0f/4096.0f) - mean*mean;
            float a = gm[ch] * rsqrtf(var + 1e-5f);
            sc[chl] = a;
            of[chl] = bm[ch] - mean*a;
        }
    }
    __syncthreads();

    float acc[16];
    #pragma unroll
    for (int k = 0; k < 16; k++) acc[k] = 0.f;
    size_t base = ((size_t)tb*1024 + g*16) * 256 + t;
    #pragma unroll
    for (int d = 0; d < 16; d++) {
        float in = g_l2[base + (size_t)d*256] * sc[d] + of[d];
        #pragma unroll
        for (int k = 0; k < 16; k++) acc[k] += in * Wsm[d*16 + k];
    }
    #pragma unroll
    for (int k = 0; k < 16; k++) g_mix[base + (size_t)k*256] = acc[k];
}

// ============================================================
// K4: inverse Haar (H then W), per-thread 4->4 butterfly + bn_inv partials
// ============================================================
__global__ void k_invhaar() {
    int tb = blockIdx.x >> 8;
    int c  = blockIdx.x & 255;
    int t  = threadIdx.x;
    int i  = t >> 4, j = t & 15;

    size_t b0 = (((size_t)tb*1024 + c)*16 + i)*16 + j;
    float LL = g_mix[b0];
    float HL = g_mix[b0 + 65536];
    float LH = g_mix[b0 + 131072];
    float HH = g_mix[b0 + 196608];

    float lo0 = RS2*(LL + HL), lo1 = RS2*(LL - HL);
    float hi0 = RS2*(LH + HH), hi1 = RS2*(LH - HH);
    float r00 = RS2*(lo0 + hi0), r01 = RS2*(lo0 - hi0);
    float r10 = RS2*(lo1 + hi1), r11 = RS2*(lo1 - hi1);

    size_t rb = (((size_t)tb*256 + c)*32 + 2*i)*32 + 2*j;
    *reinterpret_cast<float2*>(&g_rec[rb])      = make_float2(r00, r01);
    *reinterpret_cast<float2*>(&g_rec[rb + 32]) = make_float2(r10, r11);

    float s = r00 + r01 + r10 + r11;
    float q = r00*r00 + r01*r01 + r10*r10 + r11*r11;
    #pragma unroll
    for (int off = 16; off; off >>= 1) {
        s += __shfl_down_sync(0xffffffffu, s, off);
        q += __shfl_down_sync(0xffffffffu, q, off);
    }
    __shared__ float2 wsum[8];
    if ((t & 31) == 0) wsum[t >> 5] = make_float2(s, q);
    __syncthreads();
    if (t == 0) {
        float S = 0.f, Q = 0.f;
        #pragma unroll
        for (int k = 0; k < 8; k++) { S += wsum[k].x; Q += wsum[k].y; }
        g_part_inv[c*16 + tb] = make_float2(S, Q);
    }
}

// ============================================================
// K5: grouped 1x1 conv (bias cancelled by BN) + bn_c1 partials
// ============================================================
__global__ void k_conv1(const float* __restrict__ w1) {
    int im = blockIdx.x;
    int tb = im >> 4, nb = im & 15;
    __shared__ float Wsm[256];
    int t = threadIdx.x;
    Wsm[t] = w1[t];
    __syncthreads();
    size_t sbase = ((size_t)tb*256 + nb*16) * 1024;

    float sl[16], sq[16];
    #pragma unroll
    for (int o = 0; o < 16; o++) { sl[o] = 0.f; sq[o] = 0.f; }

    for (int p = t; p < 1024; p += 256) {
        float sin[16];
        #pragma unroll
        for (int i = 0; i < 16; i++) sin[i] = g_s[sbase + (size_t)i*1024 + p];
        #pragma unroll
        for (int o = 0; o < 16; o++) {
            float a = 0.f;
            #pragma unroll
            for (int i = 0; i < 16; i++) a += Wsm[o*16 + i] * sin[i];
            g_c1[sbase + (size_t)o*1024 + p] = a;
            sl[o] += a; sq[o] += a*a;
        }
    }

    __shared__ float2 wpart[8][16];
    #pragma unroll
    for (int o = 0; o < 16; o++) {
        float s = sl[o], q = sq[o];
        #pragma unroll
        for (int off = 16; off; off >>= 1) {
            s += __shfl_down_sync(0xffffffffu, s, off);
            q += __shfl_down_sync(0xffffffffu, q, off);
        }
        if ((t & 31) == 0) wpart[t >> 5][o] = make_float2(s, q);
    }
    __syncthreads();
    if (t < 16) {
        float s = 0.f, q = 0.f;
        #pragma unroll
        for (int wdx = 0; wdx < 8; wdx++) { s += wpart[wdx][t].x; q += wpart[wdx][t].y; }
        g_part_c1[(nb*16 + t)*16 + tb] = make_float2(s, q);
    }
}

// ============================================================
// K6: grouped 3x3 SAME conv + bn_c2 partials.
// smem tile stride 35 (conflict-free), 2 phases of 8 channels.
// ============================================================
#define TROW 35
#define TCH  (34 * TROW)

__global__ __launch_bounds__(512) void k_conv2(const float* __restrict__ w2) {
    int im = blockIdx.x;
    int tb = im >> 4, nb = im & 15;
    __shared__ float tile[8 * TCH];
    __shared__ float Wsm[2304];
    int tid = threadIdx.x;

    for (int idx = tid; idx < 2304; idx += 512) Wsm[idx] = w2[idx];
    for (int idx = tid; idx < 8 * TCH; idx += 512) tile[idx] = 0.f;

    size_t sbase = ((size_t)tb*256 + nb*16) * 1024;
    int o = tid >> 5, h = tid & 31;

    float acc[32];
    #pragma unroll
    for (int w = 0; w < 32; w++) acc[w] = 0.f;

    for (int ph = 0; ph < 2; ph++) {
        __syncthreads();
        for (int idx4 = tid; idx4 < 2048; idx4 += 512) {
            int ii  = idx4 >> 8;
            int rem = idx4 & 255;
            int hh  = rem >> 3;
            int ww4 = (rem & 7) * 4;
            float4 v = *reinterpret_cast<const float4*>(
                &g_s[sbase + (size_t)(ph*8 + ii)*1024 + hh*32 + ww4]);
            float* dst = &tile[ii*TCH + (hh+1)*TROW + ww4 + 1];
            dst[0] = v.x; dst[1] = v.y; dst[2] = v.z; dst[3] = v.w;
        }
        __syncthreads();

        for (int ii = 0; ii < 8; ii++) {
            int ic = ph*8 + ii;
            float wk[9];
            #pragma unroll
            for (int k = 0; k < 9; k++) wk[k] = Wsm[o*144 + ic*9 + k];
            #pragma unroll
            for (int ky = 0; ky < 3; ky++) {
                const float* row = &tile[ii*TCH + (h + ky)*TROW];
                float t0 = row[0], t1 = row[1];
                #pragma unroll
                for (int w = 0; w < 32; w++) {
                    float t2 = row[w + 2];
                    acc[w] += wk[ky*3] * t0 + wk[ky*3+1] * t1 + wk[ky*3+2] * t2;
                    t0 = t1; t1 = t2;
                }
            }
        }
    }

    size_t ob = sbase + (size_t)o*1024 + h*32;
    float s = 0.f, q = 0.f;
    #pragma unroll
    for (int w = 0; w < 32; w++) {
        g_c2[ob + w] = acc[w];
        s += acc[w]; q += acc[w]*acc[w];
    }
    #pragma unroll
    for (int off = 16; off; off >>= 1) {
        s += __shfl_down_sync(0xffffffffu, s, off);
        q += __shfl_down_sync(0xffffffffu, q, off);
    }
    if ((tid & 31) == 0) g_part_c2[(nb*16 + o)*16 + tb] = make_float2(s, q);
}

// ============================================================
// K7: inline inv/c1/c2 stats + out = BN(rec)+BN(c1)+BN(c2). float4.
// block <-> (tb, ch): exactly one channel (1024 elems) per block.
// ============================================================
__global__ void k_final(float* __restrict__ out,
                        const float* __restrict__ gi, const float* __restrict__ bi,
                        const float* __restrict__ g1, const float* __restrict__ b1,
                        const float* __restrict__ g2, const float* __restrict__ b2) {
    int blk = blockIdx.x, t = threadIdx.x;
    int ch = blk & 255;
    __shared__ float2 cf[3];
    if (t < 48) {
        int w_ = t >> 4, slot = t & 15;
        const float2* part = (w_ == 0) ? g_part_inv : (w_ == 1) ? g_part_c1 : g_part_c2;
        float2 p = part[ch*16 + slot];
        float s = p.x, q = p.y;
        unsigned mask = (t < 32) ? 0xffffffffu : 0x0000ffffu;
        #pragma unroll
        for (int off = 8; off; off >>= 1) {
            s += __shfl_down_sync(mask, s, off, 16);
            q += __shfl_down_sync(mask, q, off, 16);
        }
        if (slot == 0) {
            float mean = s * (1.0f/16384.0f);
            float var  = q * (1.0f/16384.0f) - mean*mean;
            float gg = (w_ == 0) ? gi[ch] : (w_ == 1) ? g1[ch] : g2[ch];
            float bb = (w_ == 0) ? bi[ch] : (w_ == 1) ? b1[ch] : b2[ch];
            float a = gg * rsqrtf(var + 1e-5f);
            cf[w_] = make_float2(a, bb - mean*a);
        }
    }
    __syncthreads();

    size_t base = (size_t)blk * 1024 + t * 4;
    float4 r  = *reinterpret_cast<const float4*>(&g_rec[base]);
    float4 u1 = *reinterpret_cast<const float4*>(&g_c1[base]);
    float4 u2 = *reinterpret_cast<const float4*>(&g_c2[base]);
    float2 A = cf[0], B = cf[1], C = cf[2];
    float4 o;
    o.x = (r.x*A.x + A.y) + (u1.x*B.x + B.y) + (u2.x*C.x + C.y);
    o.y = (r.y*A.x + A.y) + (u1.y*B.x + B.y) + (u2.y*C.x + C.y);
    o.z = (r.z*A.x + A.y) + (u1.z*B.x + B.y) + (u2.z*C.x + C.y);
    o.w = (r.w*A.x + A.y) + (u1.w*B.x + B.y) + (u2.w*C.x + C.y);
    *reinterpret_cast<float4*>(&out[base]) = o;
}

// ============================================================
extern "C" void kernel_launch(void* const* d_in, const int* in_sizes, int n_in,
                              void* d_out, int out_size) {
    const float* x        = (const float*)d_in[0];
    const float* haar_w   = (const float*)d_in[1];
    const float* conv1_w  = (const float*)d_in[2];
    const float* conv2_w  = (const float*)d_in[4];
    const float* bn_fwd_g = (const float*)d_in[6];
    const float* bn_fwd_b = (const float*)d_in[7];
    const float* bn_mul_g = (const float*)d_in[8];
    const float* bn_mul_b = (const float*)d_in[9];
    const float* bn_inv_g = (const float*)d_in[10];
    const float* bn_inv_b = (const float*)d_in[11];
    const float* bn_c1_g  = (const float*)d_in[12];
    const float* bn_c1_b  = (const float*)d_in[13];
    const float* bn_c2_g  = (const float*)d_in[14];
    const float* bn_c2_b  = (const float*)d_in[15];
    float* out = (float*)d_out;

    k_lif_haarw<<<2048, 256>>>(x);
    k_haarh_gate<<<4096, 256>>>(bn_fwd_g, bn_fwd_b);
    k_mix<<<1024, 256>>>(haar_w, bn_mul_g, bn_mul_b);
    k_invhaar<<<4096, 256>>>();
    k_conv1<<<256, 256>>>(conv1_w);
    k_conv2<<<256, 512>>>(conv2_w);
    k_final<<<4096, 256>>>(out, bn_inv_g, bn_inv_b,
                           bn_c1_g, bn_c1_b, bn_c2_g, bn_c2_b);
}

// round 6
// speedup vs baseline: 1.5107x; 1.1242x over previous
#include <cuda_runtime.h>
#include <math.h>

#define RS2 0.70710678f // 1/sqrt(2)

typedef unsigned long long u64;

// packed f32x2 FMA (lanewise fp32 fma): d = a*b + d
#define FMA2(d, a, b) asm("fma.rn.f32x2 %0, %1, %2, %0;" : "+l"(d) : "l"(a), "l"(b))

__device__ __forceinline__ u64 dup2(float w) {
    u64 r;
    asm("mov.b64 %0, {%1, %1};" : "=l"(r) : "r"(__float_as_uint(w)));
    return r;
}

// ---- scratch (device globals; no allocation allowed) ----
__device__ float g_s  [4*4*256*32*32];      // spikes (0/1)
__device__ float g_l1 [16*512*32*16];       // pre-BN level-1 coeffs
__device__ float g_l2 [16*1024*16*16];      // pre-BN level-2 coeffs
__device__ float g_rec[16*256*32*32];       // pre-BN reconstruction
__device__ float g_c1 [16*256*32*32];       // pre-BN conv1 out
__device__ float g_c2 [16*256*32*32];       // pre-BN conv2 out
// per-(channel, slot) partial (sum, sumsq) — fixed slots => deterministic
__device__ float2 g_part_fwd[512*8];
__device__ float2 g_part_mul[1024*16];
__device__ float2 g_part_inv[256*16];
__device__ float2 g_part_c1 [256*16];
__device__ float2 g_part_c2 [256*16];

// ============================================================
// K1: LIF over T + Haar along W + L1 gate + bn_fwd partials
// ============================================================
__global__ void k_lif_haarw(const float* __restrict__ x) {
    int blk = blockIdx.x, t = threadIdx.x;
    int idx = blk * 256 + t;
    int wp = idx & 15;
    int h  = (idx >> 4) & 31;
    int c  = (idx >> 9) & 255;
    int b  = idx >> 17;

    float v0 = 0.f, v1 = 0.f;
    float4 ps = make_float4(0.f, 0.f, 0.f, 0.f);
    #pragma unroll
    for (int tt = 0; tt < 4; tt++) {
        size_t base = ((((size_t)tt*4 + b)*256 + c)*32 + h)*32 + 2*wp;
        float2 xx = *reinterpret_cast<const float2*>(&x[base]);
        v0 += (xx.x - v0) * 0.5f;
        float s0 = (v0 >= 1.0f) ? 1.0f : 0.0f;
        v0 *= (1.0f - s0);
        v1 += (xx.y - v1) * 0.5f;
        float s1 = (v1 >= 1.0f) ? 1.0f : 0.0f;
        v1 *= (1.0f - s1);
        *reinterpret_cast<float2*>(&g_s[base]) = make_float2(s0, s1);

        float low  = RS2 * (s0 + s1);
        float high = RS2 * (s0 - s1);
        if (fabsf(low)  < 0.5f) low  = 0.f;
        if (fabsf(high) < 0.5f) high = 0.f;
        int tb = tt*4 + b;
        size_t l1b = (((size_t)tb*512 + c)*32 + h)*16 + wp;
        g_l1[l1b]          = low;
        g_l1[l1b + 131072] = high;
        ps.x += low;  ps.y += low*low;
        ps.z += high; ps.w += high*high;
    }
    #pragma unroll
    for (int off = 16; off; off >>= 1) {
        ps.x += __shfl_down_sync(0xffffffffu, ps.x, off);
        ps.y += __shfl_down_sync(0xffffffffu, ps.y, off);
        ps.z += __shfl_down_sync(0xffffffffu, ps.z, off);
        ps.w += __shfl_down_sync(0xffffffffu, ps.w, off);
    }
    __shared__ float4 wsum[8];
    if ((t & 31) == 0) wsum[t >> 5] = ps;
    __syncthreads();
    if (t == 0) {
        float4 a = wsum[0];
        #pragma unroll
        for (int i = 1; i < 8; i++) {
            float4 w4 = wsum[i];
            a.x += w4.x; a.y += w4.y; a.z += w4.z; a.w += w4.w;
        }
        int slot = ((blk >> 9) << 1) | (blk & 1);   // b*2 + hhalf
        int cc   = (blk >> 1) & 255;
        g_part_fwd[cc*8 + slot]         = make_float2(a.x, a.y);
        g_part_fwd[(256 + cc)*8 + slot] = make_float2(a.z, a.w);
    }
}

// ============================================================
// K2: inline bn_fwd stats + Haar along H + threshold + band gate
//     + bn_mul partials. block <-> (tb, c)
// ============================================================
__global__ void k_haarh_gate(const float* __restrict__ gf,
                             const float* __restrict__ bf) {
    int tb = blockIdx.x >> 8;
    int c  = blockIdx.x & 255;
    int t  = threadIdx.x;

    __shared__ float2 coef[2];
    if (t < 16) {
        int chn = (t < 8) ? c : 256 + c;
        float2 p = g_part_fwd[chn*8 + (t & 7)];
        float s = p.x, q = p.y;
        #pragma unroll
        for (int off = 4; off; off >>= 1) {
            s += __shfl_down_sync(0xffffu, s, off, 8);
            q += __shfl_down_sync(0xffffu, q, off, 8);
        }
        if ((t & 7) == 0) {
            float mean = s * (1.0f/8192.0f);
            float var  = q * (1.0f/8192.0f) - mean*mean;
            float a = gf[chn] * rsqrtf(var + 1e-5f);
            coef[t >> 3] = make_float2(a, bf[chn] - mean*a);
        }
    }
    __syncthreads();

    int v = t >> 4, w = t & 15;
    float alo = coef[0].x, clo = coef[0].y;
    float ahi = coef[1].x, chi = coef[1].y;

    size_t lo_base = ((size_t)tb*512 + c) * 512;
    size_t hi_base = lo_base + 131072;
    float a0 = g_l1[lo_base + (2*v  )*16 + w] * alo + clo;
    float a1 = g_l1[lo_base + (2*v+1)*16 + w] * alo + clo;
    float b0 = g_l1[hi_base + (2*v  )*16 + w] * ahi + chi;
    float b1 = g_l1[hi_base + (2*v+1)*16 + w] * ahi + chi;

    float LL = RS2 * (a0 + a1);
    float HL = RS2 * (a0 - a1);
    float LH = RS2 * (b0 + b1);
    float HH = RS2 * (b0 - b1);
    if (fabsf(LL) < 0.5f) LL = 0.f;
    if (fabsf(HL) < 0.5f) HL = 0.f;
    if (fabsf(LH) < 0.5f) LH = 0.f;
    if (fabsf(HH) < 0.5f) HH = 0.f;

    float4 vs = make_float4(LL, HL, LH, HH);
    float4 vq = make_float4(LL*LL, HL*HL, LH*LH, HH*HH);
    #pragma unroll
    for (int off = 16; off; off >>= 1) {
        vs.x += __shfl_down_sync(0xffffffffu, vs.x, off);
        vs.y += __shfl_down_sync(0xffffffffu, vs.y, off);
        vs.z += __shfl_down_sync(0xffffffffu, vs.z, off);
        vs.w += __shfl_down_sync(0xffffffffu, vs.w, off);
        vq.x += __shfl_down_sync(0xffffffffu, vq.x, off);
        vq.y += __shfl_down_sync(0xffffffffu, vq.y, off);
        vq.z += __shfl_down_sync(0xffffffffu, vq.z, off);
        vq.w += __shfl_down_sync(0xffffffffu, vq.w, off);
    }
    __shared__ float4 wS[8], wQ[8];
    __shared__ float4 flags;
    if ((t & 31) == 0) { wS[t >> 5] = vs; wQ[t >> 5] = vq; }
    __syncthreads();
    if (t == 0) {
        float4 S = wS[0], Q = wQ[0];
        #pragma unroll
        for (int i = 1; i < 8; i++) {
            float4 a = wS[i], b4 = wQ[i];
            S.x += a.x;  S.y += a.y;  S.z += a.z;  S.w += a.w;
            Q.x += b4.x; Q.y += b4.y; Q.z += b4.z; Q.w += b4.w;
        }
        const float inv = 1.0f / 256.0f;
        float4 f = make_float4(Q.x*inv > 0.01f ? 1.f : 0.f,
                               Q.y*inv > 0.02f ? 1.f : 0.f,
                               Q.z*inv > 0.02f ? 1.f : 0.f,
                               Q.w*inv > 0.05f ? 1.f : 0.f);
        flags = f;
        g_part_mul[(c      )*16 + tb] = make_float2(f.x*S.x, f.x*Q.x);
        g_part_mul[(c + 256)*16 + tb] = make_float2(f.y*S.y, f.y*Q.y);
        g_part_mul[(c + 512)*16 + tb] = make_float2(f.z*S.z, f.z*Q.z);
        g_part_mul[(c + 768)*16 + tb] = make_float2(f.w*S.w, f.w*Q.w);
    }
    __syncthreads();

    size_t ob = (((size_t)tb*1024 + c)*16 + v)*16 + w;
    g_l2[ob]          = LL * flags.x;
    g_l2[ob + 65536]  = HL * flags.y;
    g_l2[ob + 131072] = LH * flags.z;
    g_l2[ob + 196608] = HH * flags.w;
}

// ============================================================
// K3 (fused): bn_mul stats + 16x16 channel mix for all 4 subbands of a
// base group + inverse Haar butterfly + bn_inv partials.
// block <-> (tb, gb) where gb = base group 0..15; thread <-> (v, w).
// g_mix scratch eliminated entirely.
// ============================================================
__global__ void k_mix_inv(const float* __restrict__ hw,
                          const float* __restrict__ gm,
                          const float* __restrict__ bm) {
    int tb = blockIdx.x >> 4;
    int gb = blockIdx.x & 15;
    int t  = threadIdx.x;

    __shared__ float Wsm[4][256];
    __shared__ float sc[64], of[64];
    __shared__ float2 wred[8][16];

    // load the 4 per-subband 16x16 mixing matrices (nb = 4*sb + gb/4)
    #pragma unroll
    for (int sb = 0; sb < 4; sb++)
        Wsm[sb][t] = hw[(4*sb + (gb >> 2)) * 256 + t];

    // finalize bn_mul coefficients for 64 channels (4 threads per channel)
    {
        int chl = t >> 2, j = t & 3;        // chl = sb*16+d
        int sb = chl >> 4, d = chl & 15;
        int ch = sb*256 + gb*16 + d;
        float s = 0.f, q = 0.f;
        #pragma unroll
        for (int k = 0; k < 4; k++) {
            float2 p = g_part_mul[ch*16 + j + 4*k];
            s += p.x; q += p.y;
        }
        s += __shfl_down_sync(0xffffffffu, s, 2, 4);
        q += __shfl_down_sync(0xffffffffu, q, 2, 4);
        s += __shfl_down_sync(0xffffffffu, s, 1, 4);
        q += __shfl_down_sync(0xffffffffu, q, 1, 4);
        if (j == 0) {
            float mean = s * (1.0f/4096.0f);
            float var  = q * (1.0f/4096.0f) - mean*mean;
            float a = gm[ch] * rsqrtf(var + 1e-5f);
            sc[chl] = a;
            of[chl] = bm[ch] - mean*a;
        }
    }
    __syncthreads();

    // channel mix for all 4 subbands at this spatial position
    float acc[4][16];
    #pragma unroll
    for (int sb = 0; sb < 4; sb++)
        #pragma unroll
        for (int k = 0; k < 16; k++) acc[sb][k] = 0.f;

    #pragma unroll
    for (int sb = 0; sb < 4; sb++) {
        size_t base = ((size_t)tb*1024 + sb*256 + gb*16) * 256 + t;
        #pragma unroll
        for (int d = 0; d < 16; d++) {
            float in = g_l2[base + (size_t)d*256] * sc[sb*16+d] + of[sb*16+d];
            #pragma unroll
            for (int k = 0; k < 16; k++) acc[sb][k] += in * Wsm[sb][d*16 + k];
        }
    }

    // inverse Haar butterfly per base channel + bn_inv partials
    int v = t >> 4, w = t & 15;
    int warp = t >> 5;
    #pragma unroll
    for (int k = 0; k < 16; k++) {
        float LL = acc[0][k], HL = acc[1][k], LH = acc[2][k], HH = acc[3][k];
        float lo0 = RS2*(LL + HL), lo1 = RS2*(LL - HL);
        float hi0 = RS2*(LH + HH), hi1 = RS2*(LH - HH);
        float r00 = RS2*(lo0 + hi0), r01 = RS2*(lo0 - hi0);
        float r10 = RS2*(lo1 + hi1), r11 = RS2*(lo1 - hi1);

        size_t rb = (((size_t)tb*256 + gb*16 + k)*32 + 2*v)*32 + 2*w;
        *reinterpret_cast<float2*>(&g_rec[rb])      = make_float2(r00, r01);
        *reinterpret_cast<float2*>(&g_rec[rb + 32]) = make_float2(r10, r11);

        float s = r00 + r01 + r10 + r11;
        float q = r00*r00 + r01*r01 + r10*r10 + r11*r11;
        #pragma unroll
        for (int off = 16; off; off >>= 1) {
            s += __shfl_down_sync(0xffffffffu, s, off);
            q += __shfl_down_sync(0xffffffffu, q, off);
        }
        if ((t & 31) == 0) wred[warp][k] = make_float2(s, q);
    }
    __syncthreads();
    if (t < 16) {
        float S = 0.f, Q = 0.f;
        #pragma unroll
        for (int wd = 0; wd < 8; wd++) { S += wred[wd][t].x; Q += wred[wd][t].y; }
        g_part_inv[(gb*16 + t)*16 + tb] = make_float2(S, Q);
    }
}

// ============================================================
// K4: grouped 1x1 conv + bn_c1 partials
// ============================================================
__global__ void k_conv1(const float* __restrict__ w1) {
    int im = blockIdx.x;
    int tb = im >> 4, nb = im & 15;
    __shared__ float Wsm[256];
    int t = threadIdx.x;
    Wsm[t] = w1[t];
    __syncthreads();
    size_t sbase = ((size_t)tb*256 + nb*16) * 1024;

    float sl[16], sq[16];
    #pragma unroll
    for (int o = 0; o < 16; o++) { sl[o] = 0.f; sq[o] = 0.f; }

    for (int p = t; p < 1024; p += 256) {
        float sin[16];
        #pragma unroll
        for (int i = 0; i < 16; i++) sin[i] = g_s[sbase + (size_t)i*1024 + p];
        #pragma unroll
        for (int o = 0; o < 16; o++) {
            float a = 0.f;
            #pragma unroll
            for (int i = 0; i < 16; i++) a += Wsm[o*16 + i] * sin[i];
            g_c1[sbase + (size_t)o*1024 + p] = a;
            sl[o] += a; sq[o] += a*a;
        }
    }

    __shared__ float2 wpart[8][16];
    #pragma unroll
    for (int o = 0; o < 16; o++) {
        float s = sl[o], q = sq[o];
        #pragma unroll
        for (int off = 16; off; off >>= 1) {
            s += __shfl_down_sync(0xffffffffu, s, off);
            q += __shfl_down_sync(0xffffffffu, q, off);
        }
        if ((t & 31) == 0) wpart[t >> 5][o] = make_float2(s, q);
    }
    __syncthreads();
    if (t < 16) {
        float s = 0.f, q = 0.f;
        #pragma unroll
        for (int wdx = 0; wdx < 8; wdx++) { s += wpart[wdx][t].x; q += wpart[wdx][t].y; }
        g_part_c1[(nb*16 + t)*16 + tb] = make_float2(s, q);
    }
}

// ============================================================
// K5: grouped 3x3 SAME conv via packed fma.rn.f32x2 (FFMA2).
// Dual smem tiles: tileA holds in[w] at rowA[w+1] (S-family pairs at even
// offsets), tileB holds in[w] at rowB[w] (E-family pairs). All packed
// operands are aligned LDS.64 — no per-iteration packing.
// Thread map: o = tid&15, h = tid>>4 => each warp reads only 2 distinct
// rows (smem broadcast across the 16 o-lanes).
// out pair p: acc_p = w0*S_p + w1*E_p + w2*S_{p+1}.
// 4 phases of 4 input channels. + bn_c2 partials.
// ============================================================
#define A_RS 36
#define A_CH (34 * A_RS)   // 1224
#define B_RS 32
#define B_CH (34 * B_RS)   // 1088

__global__ __launch_bounds__(512) void k_conv2(const float* __restrict__ w2) {
    int im = blockIdx.x;
    int tb = im >> 4, nb = im & 15;
    __shared__ __align__(16) float tileA[4 * A_CH];  // 19584 B
    __shared__ __align__(16) float tileB[4 * B_CH];  // 17408 B
    __shared__ float Wsm[2304];                      //  9216 B
    __shared__ float2 red[16][16];                   //  2048 B
    int tid = threadIdx.x;
    int o = tid & 15, h = tid >> 4;

    for (int idx = tid; idx < 2304; idx += 512) Wsm[idx] = w2[idx];
    for (int idx = tid; idx < 4 * A_CH; idx += 512) tileA[idx] = 0.f;
    for (int idx = tid; idx < 4 * B_CH; idx += 512) tileB[idx] = 0.f;

    size_t sbase = ((size_t)tb*256 + nb*16) * 1024;

    u64 acc[16];
    #pragma unroll
    for (int p = 0; p < 16; p++) acc[p] = 0ull;

    for (int ph = 0; ph < 4; ph++) {
        __syncthreads();
        // stage 4 channels into both tiles
        for (int idx4 = tid; idx4 < 1024; idx4 += 512) {
            int ii  = idx4 >> 8;
            int rem = idx4 & 255;
            int hh  = rem >> 3;
            int ww4 = (rem & 7) * 4;
            float4 val = *reinterpret_cast<const float4*>(
                &g_s[sbase + (size_t)(ph*4 + ii)*1024 + hh*32 + ww4]);
            float* dA = &tileA[ii*A_CH + (hh+1)*A_RS + ww4 + 1];
            dA[0] = val.x; dA[1] = val.y; dA[2] = val.z; dA[3] = val.w;
            *reinterpret_cast<float4*>(&tileB[ii*B_CH + (hh+1)*B_RS + ww4]) = val;
        }
        __syncthreads();

        #pragma unroll
        for (int ii = 0; ii < 4; ii++) {
            int ic = ph*4 + ii;
            u64 wpk[3][3];
            #pragma unroll
            for (int ky = 0; ky < 3; ky++)
                #pragma unroll
                for (int kx = 0; kx < 3; kx++)
                    wpk[ky][kx] = dup2(Wsm[o*144 + ic*9 + ky*3 + kx]);

            #pragma unroll
            for (int ky = 0; ky < 3; ky++) {
                const u64* A64 = reinterpret_cast<const u64*>(
                    &tileA[ii*A_CH + (h + ky)*A_RS]);
                const u64* B64 = reinterpret_cast<const u64*>(
                    &tileB[ii*B_CH + (h + ky)*B_RS]);
                u64 sp = A64[0];
                #pragma unroll
                for (int p = 0; p < 16; p++) {
                    u64 e  = B64[p];
                    u64 sn = A64[p + 1];
                    FMA2(acc[p], wpk[ky][0], sp);
                    FMA2(acc[p], wpk[ky][1], e);
                    FMA2(acc[p], wpk[ky][2], sn);
                    sp = sn;
                }
            }
        }
    }

    // store + bn_c2 partials
    size_t ob = sbase + (size_t)o*1024 + h*32;
    u64* outp = reinterpret_cast<u64*>(&g_c2[ob]);
    float s = 0.f, q = 0.f;
    #pragma unroll
    for (int p = 0; p < 16; p++) {
        u64 a = acc[p];
        outp[p] = a;
        float lo = __uint_as_float((unsigned)(a & 0xffffffffu));
        float hi = __uint_as_float((unsigned)(a >> 32));
        s += lo + hi;
        q += lo*lo + hi*hi;
    }
    // combine the two h-lanes in each warp (lane = (h&1)*16 + o)
    s += __shfl_xor_sync(0xffffffffu, s, 16);
    q += __shfl_xor_sync(0xffffffffu, q, 16);
    if ((tid & 31) < 16) red[tid >> 5][o] = make_float2(s, q);
    __syncthreads();
    if (tid < 16) {
        float S = 0.f, Q = 0.f;
        #pragma unroll
        for (int wd = 0; wd < 16; wd++) { S += red[wd][tid].x; Q += red[wd][tid].y; }
        g_part_c2[(nb*16 + tid)*16 + tb] = make_float2(S, Q);
    }
}

// ============================================================
// K6: inline inv/c1/c2 stats + out = BN(rec)+BN(c1)+BN(c2). float4.
// ============================================================
__global__ void k_final(float* __restrict__ out,
                        const float* __restrict__ gi, const float* __restrict__ bi,
                        const float* __restrict__ g1, const float* __restrict__ b1,
                        const float* __restrict__ g2, const float* __restrict__ b2) {
    int blk = blockIdx.x, t = threadIdx.x;
    int ch = blk & 255;
    __shared__ float2 cf[3];
    if (t < 48) {
        int w_ = t >> 4, slot = t & 15;
        const float2* part = (w_ == 0) ? g_part_inv : (w_ == 1) ? g_part_c1 : g_part_c2;
        float2 p = part[ch*16 + slot];
        float s = p.x, q = p.y;
        unsigned mask = (t < 32) ? 0xffffffffu : 0x0000ffffu;
        #pragma unroll
        for (int off = 8; off; off >>= 1) {
            s += __shfl_down_sync(mask, s, off, 16);
            q += __shfl_down_sync(mask, q, off, 16);
        }
        if (slot == 0) {
            float mean = s * (1.0f/16384.0f);
            float var  = q * (1.0f/16384.0f) - mean*mean;
            float gg = (w_ == 0) ? gi[ch] : (w_ == 1) ? g1[ch] : g2[ch];
            float bb = (w_ == 0) ? bi[ch] : (w_ == 1) ? b1[ch] : b2[ch];
            float a = gg * rsqrtf(var + 1e-5f);
            cf[w_] = make_float2(a, bb - mean*a);
        }
    }
    __syncthreads();

    size_t base = (size_t)blk * 1024 + t * 4;
    float4 r  = *reinterpret_cast<const float4*>(&g_rec[base]);
    float4 u1 = *reinterpret_cast<const float4*>(&g_c1[base]);
    float4 u2 = *reinterpret_cast<const float4*>(&g_c2[base]);
    float2 A = cf[0], B = cf[1], C = cf[2];
    float4 o;
    o.x = (r.x*A.x + A.y) + (u1.x*B.x + B.y) + (u2.x*C.x + C.y);
    o.y = (r.y*A.x + A.y) + (u1.y*B.x + B.y) + (u2.y*C.x + C.y);
    o.z = (r.z*A.x + A.y) + (u1.z*B.x + B.y) + (u2.z*C.x + C.y);
    o.w = (r.w*A.x + A.y) + (u1.w*B.x + B.y) + (u2.w*C.x + C.y);
    *reinterpret_cast<float4*>(&out[base]) = o;
}

// ============================================================
extern "C" void kernel_launch(void* const* d_in, const int* in_sizes, int n_in,
                              void* d_out, int out_size) {
    const float* x        = (const float*)d_in[0];
    const float* haar_w   = (const float*)d_in[1];
    const float* conv1_w  = (const float*)d_in[2];
    const float* conv2_w  = (const float*)d_in[4];
    const float* bn_fwd_g = (const float*)d_in[6];
    const float* bn_fwd_b = (const float*)d_in[7];
    const float* bn_mul_g = (const float*)d_in[8];
    const float* bn_mul_b = (const float*)d_in[9];
    const float* bn_inv_g = (const float*)d_in[10];
    const float* bn_inv_b = (const float*)d_in[11];
    const float* bn_c1_g  = (const float*)d_in[12];
    const float* bn_c1_b  = (const float*)d_in[13];
    const float* bn_c2_g  = (const float*)d_in[14];
    const float* bn_c2_b  = (const float*)d_in[15];
    float* out = (float*)d_out;

    k_lif_haarw<<<2048, 256>>>(x);
    k_haarh_gate<<<4096, 256>>>(bn_fwd_g, bn_fwd_b);
    k_mix_inv<<<256, 256>>>(haar_w, bn_mul_g, bn_mul_b);
    k_conv1<<<256, 256>>>(conv1_w);
    k_conv2<<<256, 512>>>(conv2_w);
    k_final<<<4096, 256>>>(out, bn_inv_g, bn_inv_b,
                           bn_c1_g, bn_c1_b, bn_c2_g, bn_c2_b);
}